// round 6
// baseline (speedup 1.0000x reference)
#include <cuda_runtime.h>

// ---------------- problem constants (fixed shapes) ----------------
#define B_    4
#define D_    118
#define H_    32              // == warp size: lane <-> h
#define W_    88
#define C_    80
#define NX_   360
#define NY_   360
#define XY_   (NX_ * NY_)     // 129600
#define NCOLB (D_ * W_)       // 10,384 ray columns per batch
#define CPB   12              // columns per block (phase2: 12*20=240 tasks)

// ---------------- kernel 1: zero one batch slice of d_out ------------------
__global__ void zero_out_kernel(float4* __restrict__ o) {
    size_t i = (size_t)blockIdx.x * blockDim.x + threadIdx.x;
    o[i] = make_float4(0.f, 0.f, 0.f, 0.f);   // grid sized exactly: no guard
}

// ---------------- kernel 2: two-phase column scatter, one batch ------------
// Structural fact (validated R5): combine[0][1] == combine[1][1] == 0 exactly
// in fp32, so gx,gy are identical across the 32 h's of a (b,d,w) column; only
// the cz==0 test varies per h. Phase 1: warps compute per-column pass masks +
// voxel (ballot over h == lane), with an exact per-h fallback if uniformity
// ever breaks. Phase 2: 240 threads each aggregate one (column, 4-channel)
// float4 over the passing h's and commit 4 scalar atomics straight into the
// final (B,C,X,Y) layout.
__global__ void __launch_bounds__(256)
scatter_kernel(const float* __restrict__ x, const float* __restrict__ frustum,
               float* __restrict__ out,
               const float* __restrict__ rots,
               const float* __restrict__ trans,
               const float* __restrict__ intrins, int b) {
    __shared__ float s_cmb[9];
    __shared__ float s_tr[3];
    __shared__ unsigned s_mask[CPB];
    __shared__ int s_cx[CPB], s_cy[CPB];

    int tid  = threadIdx.x;
    int wid  = tid >> 5;
    int lane = tid & 31;                 // lane == h in phase 1

    // --- block setup: combine = rots[b] @ inv(intrins[b]) (double adjugate) ---
    if (tid == 0) {
        const float* K = intrins + b * 9;
        double a00 = K[0], a01 = K[1], a02 = K[2];
        double a10 = K[3], a11 = K[4], a12 = K[5];
        double a20 = K[6], a21 = K[7], a22 = K[8];
        double det = a00 * (a11 * a22 - a12 * a21)
                   - a01 * (a10 * a22 - a12 * a20)
                   + a02 * (a10 * a21 - a11 * a20);
        double id = 1.0 / det;
        float inv[9];
        inv[0] = (float)(( a11 * a22 - a12 * a21) * id);
        inv[1] = (float)((-(a01 * a22 - a02 * a21)) * id);
        inv[2] = (float)(( a01 * a12 - a02 * a11) * id);
        inv[3] = (float)((-(a10 * a22 - a12 * a20)) * id);
        inv[4] = (float)(( a00 * a22 - a02 * a20) * id);
        inv[5] = (float)((-(a00 * a12 - a02 * a10)) * id);
        inv[6] = (float)(( a10 * a21 - a11 * a20) * id);
        inv[7] = (float)((-(a00 * a21 - a01 * a20)) * id);
        inv[8] = (float)(( a00 * a11 - a01 * a10) * id);
        const float* R = rots + b * 9;
        #pragma unroll
        for (int i = 0; i < 3; i++)
            #pragma unroll
            for (int j = 0; j < 3; j++)
                s_cmb[i * 3 + j] = R[i * 3 + 0] * inv[0 * 3 + j]
                                 + R[i * 3 + 1] * inv[1 * 3 + j]
                                 + R[i * 3 + 2] * inv[2 * 3 + j];
        s_tr[0] = trans[b * 3 + 0];
        s_tr[1] = trans[b * 3 + 1];
        s_tr[2] = trans[b * 3 + 2];
    }
    __syncthreads();

    int col0 = blockIdx.x * CPB;

    // --------------- phase 1: masks + voxel per column ----------------------
    for (int cl = wid; cl < CPB; cl += 8) {
        int col = col0 + cl;             // local to batch: col = d*W + w
        if (col >= NCOLB) { if (lane == 0) s_mask[cl] = 0u; continue; }
        int w = col % W_;
        int d = col / W_;

        const float* fr = frustum + ((size_t)(d * H_ + lane) * W_ + w) * 3;
        float fu = fr[0];                // uniform across lanes
        float fv = fr[1];                // per-lane (h)
        float fd = fr[2];                // uniform across lanes
        float p0 = fu * fd, p1 = fv * fd, p2 = fd;

        float gx = s_cmb[0] * p0 + s_cmb[1] * p1 + s_cmb[2] * p2 + s_tr[0];
        float gy = s_cmb[3] * p0 + s_cmb[4] * p1 + s_cmb[5] * p2 + s_tr[1];
        float gz = s_cmb[6] * p0 + s_cmb[7] * p1 + s_cmb[8] * p2 + s_tr[2];

        // matches ((geom - BX_LO)/DX).astype(int32): trunc toward zero,
        // incl. the (-1,0)->0 "kept" quirk of the reference
        int cx = (int)((gx + 54.0f) / 0.3f);
        int cy = (int)((gy + 54.0f) / 0.3f);
        int cz = (int)((gz + 10.0f) / 20.0f);

        bool pass = (unsigned)cx < (unsigned)NX_ && (unsigned)cy < (unsigned)NY_
                    && cz == 0;
        unsigned mask = __ballot_sync(0xFFFFFFFFu, pass);
        if (mask == 0u) { if (lane == 0) s_mask[cl] = 0u; continue; }

        int src = __ffs(mask) - 1;
        int cx0 = __shfl_sync(0xFFFFFFFFu, cx, src);
        int cy0 = __shfl_sync(0xFFFFFFFFu, cy, src);
        bool uni = __all_sync(0xFFFFFFFFu, !pass || (cx == cx0 && cy == cy0));

        if (uni) {
            if (lane == 0) { s_mask[cl] = mask; s_cx[cl] = cx0; s_cy[cl] = cy0; }
        } else {
            // exact fallback (never expected): per-h scalar scatter now
            if (lane == 0) s_mask[cl] = 0u;
            size_t xbase = ((size_t)((b * D_ + d) * H_) * W_ + w) * (size_t)C_;
            for (int h = 0; h < H_; h++) {
                if (!((mask >> h) & 1u)) continue;
                int cxh = __shfl_sync(0xFFFFFFFFu, cx, h);
                int cyh = __shfl_sync(0xFFFFFFFFu, cy, h);
                size_t q = (size_t)cxh * NY_ + cyh;
                const float* xr = x + xbase + (size_t)h * (W_ * C_);
                for (int c = lane; c < C_; c += 32)
                    atomicAdd(out + ((size_t)b * C_ + c) * XY_ + q, xr[c]);
            }
        }
    }
    __syncthreads();

    // --------------- phase 2: aggregate + commit (240 tasks) ----------------
    if (tid >= CPB * (C_ / 4)) return;
    int cl = tid / (C_ / 4);             // column within block
    int g  = tid % (C_ / 4);             // 4-channel group 0..19
    unsigned mask = s_mask[cl];
    if (mask == 0u) return;

    int col = col0 + cl;
    int w = col % W_;
    int d = col / W_;
    size_t xbase = ((size_t)((b * D_ + d) * H_) * W_ + w) * (size_t)C_ + 4 * g;

    float4 acc = make_float4(0.f, 0.f, 0.f, 0.f);
    #pragma unroll
    for (int h = 0; h < H_; h++) {
        if ((mask >> h) & 1u) {
            float4 v = __ldcs(reinterpret_cast<const float4*>(
                x + xbase + (size_t)h * (W_ * C_)));
            acc.x += v.x; acc.y += v.y; acc.z += v.z; acc.w += v.w;
        }
    }

    size_t q  = (size_t)s_cx[cl] * NY_ + s_cy[cl];
    float* op = out + ((size_t)b * C_ + 4 * g) * XY_ + q;
    atomicAdd(op,                   acc.x);
    atomicAdd(op + (size_t)XY_,     acc.y);
    atomicAdd(op + 2 * (size_t)XY_, acc.z);
    atomicAdd(op + 3 * (size_t)XY_, acc.w);
}

// ---------------- launch ----------------------------------------------------
extern "C" void kernel_launch(void* const* d_in, const int* in_sizes, int n_in,
                              void* d_out, int out_size) {
    const float* x       = (const float*)d_in[0];
    const float* rots    = (const float*)d_in[1];
    const float* trans   = (const float*)d_in[2];
    const float* intrins = (const float*)d_in[3];
    const float* frustum = (const float*)d_in[4];
    float* out = (float*)d_out;

    // per-batch slice: C*XY = 10,368,000 floats = 2,592,000 float4 = 10125*256
    const int ZBLK = (C_ * XY_) / 4 / 256;
    const int SBLK = (NCOLB + CPB - 1) / CPB;   // 866

    // Interleave so batch b's freshly-zeroed 41.5MB out-slice is L2-resident
    // when the scatter atomics RMW it.
    for (int b = 0; b < B_; b++) {
        zero_out_kernel<<<ZBLK, 256>>>(
            reinterpret_cast<float4*>(out) + (size_t)b * (C_ * XY_ / 4));
        scatter_kernel<<<SBLK, 256>>>(x, frustum, out, rots, trans, intrins, b);
    }
}

// round 7
// speedup vs baseline: 1.2293x; 1.2293x over previous
#include <cuda_runtime.h>

// ---------------- problem constants (fixed shapes) ----------------
#define B_    4
#define D_    118
#define H_    32              // == warp size: lane <-> h
#define W_    88
#define C_    80
#define NX_   360
#define NY_   360
#define XY_   (NX_ * NY_)     // 129600
#define NCOLB (D_ * W_)       // 10,384 columns per batch (divisible by 8)
#define NCOL  (B_ * NCOLB)    // 41,536 ray columns

// ---------------- kernel 1: zero all of d_out (poisoned 0xAA) --------------
__global__ void zero_out_kernel(float4* __restrict__ o) {
    size_t i = (size_t)blockIdx.x * blockDim.x + threadIdx.x;
    o[i] = make_float4(0.f, 0.f, 0.f, 0.f);   // grid sized exactly: no guard
}

// ---------------- kernel 2: warp-per-ray-column aggregated scatter ---------
// Structural fact (validated R5/R6): combine[0][1] == combine[1][1] == 0
// exactly in fp32 (K upper-triangular, (Ryaw@Rbase) rows 0,1 have zero middle
// entry), so gx,gy are identical across the 32 h's of a (b,d,w) column; only
// the cz==0 test varies with h. One warp aggregates a whole column in
// registers and commits ONE feature vector with scalar atomics straight into
// the final (B,C,X,Y) layout. Uniformity check + exact per-h fallback guard
// the assumption. Each 8-warp block lies entirely within one batch
// (NCOLB % 8 == 0), so thread 0 computes combine = rots[b] @ inv(K[b]) into
// smem once per block (replaces the separate setup launch).
__global__ void __launch_bounds__(256)
scatter_kernel(const float* __restrict__ x, const float* __restrict__ frustum,
               float* __restrict__ out,
               const float* __restrict__ rots,
               const float* __restrict__ trans,
               const float* __restrict__ intrins) {
    __shared__ float s_cmb[9];
    __shared__ float s_tr[3];

    int tid  = threadIdx.x;
    int lane = tid & 31;                     // lane == h
    int col  = blockIdx.x * 8 + (tid >> 5);  // one column per warp
    int w = col % W_;
    int t = col / W_;
    int d = t % D_;
    int b = t / D_;                          // uniform across the block

    // --- per-block setup: combine = rots[b] @ inv(intrins[b]) (dbl adjugate)
    if (tid == 0) {
        const float* K = intrins + b * 9;
        double a00 = K[0], a01 = K[1], a02 = K[2];
        double a10 = K[3], a11 = K[4], a12 = K[5];
        double a20 = K[6], a21 = K[7], a22 = K[8];
        double det = a00 * (a11 * a22 - a12 * a21)
                   - a01 * (a10 * a22 - a12 * a20)
                   + a02 * (a10 * a21 - a11 * a20);
        double id = 1.0 / det;
        float inv[9];
        inv[0] = (float)(( a11 * a22 - a12 * a21) * id);
        inv[1] = (float)((-(a01 * a22 - a02 * a21)) * id);
        inv[2] = (float)(( a01 * a12 - a02 * a11) * id);
        inv[3] = (float)((-(a10 * a22 - a12 * a20)) * id);
        inv[4] = (float)(( a00 * a22 - a02 * a20) * id);
        inv[5] = (float)((-(a00 * a12 - a02 * a10)) * id);
        inv[6] = (float)(( a10 * a21 - a11 * a20) * id);
        inv[7] = (float)((-(a00 * a21 - a01 * a20)) * id);
        inv[8] = (float)(( a00 * a11 - a01 * a10) * id);
        const float* R = rots + b * 9;
        #pragma unroll
        for (int i = 0; i < 3; i++)
            #pragma unroll
            for (int j = 0; j < 3; j++)
                s_cmb[i * 3 + j] = R[i * 3 + 0] * inv[0 * 3 + j]
                                 + R[i * 3 + 1] * inv[1 * 3 + j]
                                 + R[i * 3 + 2] * inv[2 * 3 + j];
        s_tr[0] = trans[b * 3 + 0];
        s_tr[1] = trans[b * 3 + 1];
        s_tr[2] = trans[b * 3 + 2];
    }
    __syncthreads();

    // frustum (D,H,W,3): [...,0]=u (w only), [...,1]=v (h only), [...,2]=depth
    const float* fr = frustum + ((size_t)(d * H_ + lane) * W_ + w) * 3;
    float fu = fr[0];     // uniform across lanes
    float fv = fr[1];     // per-lane (h)
    float fd = fr[2];     // uniform across lanes
    float p0 = fu * fd, p1 = fv * fd, p2 = fd;

    float gx = s_cmb[0] * p0 + s_cmb[1] * p1 + s_cmb[2] * p2 + s_tr[0];
    float gy = s_cmb[3] * p0 + s_cmb[4] * p1 + s_cmb[5] * p2 + s_tr[1];
    float gz = s_cmb[6] * p0 + s_cmb[7] * p1 + s_cmb[8] * p2 + s_tr[2];

    // matches ((geom - BX_LO)/DX).astype(int32): trunc toward zero,
    // incl. the (-1,0)->0 "kept" quirk of the reference
    int cx = (int)((gx + 54.0f) / 0.3f);
    int cy = (int)((gy + 54.0f) / 0.3f);
    int cz = (int)((gz + 10.0f) / 20.0f);

    bool pass = (unsigned)cx < (unsigned)NX_ && (unsigned)cy < (unsigned)NY_
                && cz == 0;
    unsigned mask = __ballot_sync(0xFFFFFFFFu, pass);
    if (mask == 0u) return;                  // whole column rejected: skip x

    int src = __ffs(mask) - 1;
    int cx0 = __shfl_sync(0xFFFFFFFFu, cx, src);
    int cy0 = __shfl_sync(0xFFFFFFFFu, cy, src);
    bool uni = __all_sync(0xFFFFFFFFu, !pass || (cx == cx0 && cy == cy0));

    size_t xbase = ((size_t)((b * D_ + d) * H_) * W_ + w) * (size_t)C_; // h=0

    if (uni) {
        // lanes 0..19: accumulate one float4 channel group over passing h's
        if (lane < C_ / 4) {
            const float* xp = x + xbase + 4 * lane;
            float4 acc = make_float4(0.f, 0.f, 0.f, 0.f);
            #pragma unroll
            for (int h = 0; h < H_; h++) {
                if ((mask >> h) & 1u) {
                    float4 v = __ldcs(reinterpret_cast<const float4*>(
                        xp + (size_t)h * (W_ * C_)));
                    acc.x += v.x; acc.y += v.y; acc.z += v.z; acc.w += v.w;
                }
            }
            size_t q  = (size_t)cx0 * NY_ + cy0;
            float* op = out + ((size_t)b * C_ + 4 * lane) * XY_ + q;
            atomicAdd(op,                   acc.x);
            atomicAdd(op + (size_t)XY_,     acc.y);
            atomicAdd(op + 2 * (size_t)XY_, acc.z);
            atomicAdd(op + 3 * (size_t)XY_, acc.w);
        }
    } else {
        // exact fallback (never expected): per-h scalar scatter
        for (int h = 0; h < H_; h++) {
            if (!((mask >> h) & 1u)) continue;
            int cxh = __shfl_sync(0xFFFFFFFFu, cx, h);
            int cyh = __shfl_sync(0xFFFFFFFFu, cy, h);
            size_t q = (size_t)cxh * NY_ + cyh;
            const float* xr = x + xbase + (size_t)h * (W_ * C_);
            for (int c = lane; c < C_; c += 32)
                atomicAdd(out + ((size_t)b * C_ + c) * XY_ + q, xr[c]);
        }
    }
}

// ---------------- launch ----------------------------------------------------
extern "C" void kernel_launch(void* const* d_in, const int* in_sizes, int n_in,
                              void* d_out, int out_size) {
    const float* x       = (const float*)d_in[0];
    const float* rots    = (const float*)d_in[1];
    const float* trans   = (const float*)d_in[2];
    const float* intrins = (const float*)d_in[3];
    const float* frustum = (const float*)d_in[4];
    float* out = (float*)d_out;

    // 41,472,000 floats = 10,368,000 float4 = 40500 * 256 exactly
    zero_out_kernel<<<40500, 256>>>(reinterpret_cast<float4*>(out));

    // one warp per (b,d,w) column: 41536 warps, 8 per 256-thread block
    scatter_kernel<<<NCOL / 8, 256>>>(x, frustum, out, rots, trans, intrins);
}